// round 12
// baseline (speedup 1.0000x reference)
#include <cuda_runtime.h>
#include <cstdint>

// ---------------- problem constants ----------------
#define NATOMS   50000
#define S        7
#define NRBF     16
#define NPAIRS   28        // S*(S+1)/2
#define SUB      32        // NA*NZ
#define COLS     1008      // S*NRBF + NPAIRS*SUB
#define ANG_OFF  112       // S*NRBF
#define RC       0.51f
#define RMIN     0.08f
#define RCA      0.35f
#define RAMIN    0.08f
#define NA       8
#define NZ       4
#define ETA_R    1970.0f
#define ZETA     14.1f
#define PI_F     3.14159265358979323846f
#define PI_OVER_RC   (PI_F / RC)
#define PI_OVER_RCA  (PI_F / RCA)
#define DSTEP_R  0.026875f       // (RC-RMIN)/NRBF
#define DSTEP_A  0.03375f        // (RCA-RAMIN)/NA
#define ETA_A_LOG2E 1803.3688011112043f  // ETA_A * log2(e)

#define MAXP     1000000
#define PA_CONST 200000

// vector float atomic (sm_90+): one 16B reduction per lane
#define RED4(ptr, v)                                                          \
    asm volatile("red.global.add.v4.f32 [%0], {%1,%2,%3,%4};"                 \
                 :: "l"(ptr), "f"((v).x), "f"((v).y), "f"((v).z), "f"((v).w)  \
                 : "memory")

// 16B record per angular pair: (rx, ry, rz, fc-with-spec-in-low-6-mantissa-bits)
__device__ float4 g_rec[PA_CONST];
// radial scatter bases per pair (computed once, read coalesced)
__device__ uint2  g_base[MAXP];

// ======= kernel A: zero-fill || per-pair precompute (all P) =======
__global__ __launch_bounds__(256)
void fusedA_kernel(const int* __restrict__ atom_index,
                   const int* __restrict__ pairs,   // [2, P]
                   const float* __restrict__ d_ij,  // [P]
                   const float* __restrict__ r_ij,  // [P,3]
                   float4* __restrict__ out4,
                   int P, int PA, int zblocks, int n4)
{
    if ((int)blockIdx.x < zblocks) {
        int stride = zblocks * 256;
        for (int i = blockIdx.x * 256 + threadIdx.x; i < n4; i += stride)
            out4[i] = make_float4(0.f, 0.f, 0.f, 0.f);
        return;
    }
    int p = (blockIdx.x - zblocks) * 256 + threadIdx.x;
    if (p >= P) return;

    int i  = pairs[p];
    int j  = pairs[P + p];
    int si = atom_index[i];
    int sj = atom_index[j];

    g_base[p] = make_uint2((unsigned)(i * COLS + sj * NRBF),
                           (unsigned)(j * COLS + si * NRBF));

    if (p < PA) {
        float d  = d_ij[p];
        float fc = (d < RCA) ? (0.5f * __cosf(PI_OVER_RCA * d) + 0.5f) : 0.0f;
        unsigned u = (__float_as_uint(fc) & 0xFFFFFFC0u)
                   | (unsigned)((si << 3) | sj);
        g_rec[p] = make_float4(r_ij[3 * p + 0], r_ij[3 * p + 1], r_ij[3 * p + 2],
                               __uint_as_float(u));
    }
}

// ======= kernel B: angular || radial, Bresenham-interleaved =======
__global__ __launch_bounds__(256)
void fusedB_kernel(const int* __restrict__ central,
                   const int* __restrict__ pidx,    // [2, T]
                   const int* __restrict__ sign12,  // [2, T]
                   const float* __restrict__ d_ij,
                   float* __restrict__ out,
                   int P, int T, int ablocks, int total)
{
    int b = blockIdx.x;
    // Bresenham split: angular blocks spread evenly through the grid
    int a_lo = (int)((long long)b * ablocks / total);
    int a_hi = (int)(((long long)b + 1) * ablocks / total);
    bool is_ang = (a_hi > a_lo);

    if (is_ang) {
        // ---------------- angular partition: 256 triples/block ----------------
        __shared__ __align__(16) float s_f1[256 * 4];   // pref*f1[zz], STS.128
        __shared__ float s_sd[256];                     // 0.5*(d0+d1)
        __shared__ int   s_base[256];

        int tid = threadIdx.x;
        int q   = a_lo;
        int t0  = q * 256;
        int t   = t0 + tid;

        if (t < T) {
            int p0  = pidx[t];
            int p1  = pidx[T + t];
            int sg0 = sign12[t];
            int sg1 = sign12[T + t];
            int c   = central[t];

            float4 r0 = g_rec[p0];      // one scattered LDG.128 each
            float4 r1 = g_rec[p1];

            // reconstruct d, 1/d from r (reference also norms r_ij)
            float dd0 = fmaf(r0.x, r0.x, fmaf(r0.y, r0.y, r0.z * r0.z));
            float dd1 = fmaf(r1.x, r1.x, fmaf(r1.y, r1.y, r1.z * r1.z));
            float inv0 = rsqrtf(dd0);
            float inv1 = rsqrtf(dd1);

            unsigned b0 = __float_as_uint(r0.w);
            unsigned b1 = __float_as_uint(r1.w);
            int   sp0 = (int)(b0 & 63u);
            int   sp1 = (int)(b1 & 63u);
            float fc0 = __uint_as_float(b0 & 0xFFFFFFC0u);
            float fc1 = __uint_as_float(b1 & 0xFFFFFFC0u);

            float dot  = r0.x * r1.x + r0.y * r1.y + r0.z * r1.z;
            float ss   = (sg0 == sg1) ? 0.95f : -0.95f;
            float cosa = ss * dot * inv0 * inv1;
            float sina = sqrtf(fmaxf(0.0f, 1.0f - cosa * cosa));
            float pref = 2.0f * fc0 * fc1;

            // f1[zz] via cos(angle - shfz) = cosa*cos(shfz) + sina*sin(shfz)
            const float CZ[4] = { 0.92387953251f,  0.38268343236f,
                                 -0.38268343236f, -0.92387953251f };
            const float SZ[4] = { 0.38268343236f,  0.92387953251f,
                                  0.92387953251f,  0.38268343236f };
            float4 f1v;
            {
                float u0 = fmaxf(0.0f, fmaf(0.5f * CZ[0], cosa, fmaf(0.5f * SZ[0], sina, 0.5f)));
                float u1 = fmaxf(0.0f, fmaf(0.5f * CZ[1], cosa, fmaf(0.5f * SZ[1], sina, 0.5f)));
                float u2 = fmaxf(0.0f, fmaf(0.5f * CZ[2], cosa, fmaf(0.5f * SZ[2], sina, 0.5f)));
                float u3 = fmaxf(0.0f, fmaf(0.5f * CZ[3], cosa, fmaf(0.5f * SZ[3], sina, 0.5f)));
                f1v.x = pref * exp2f(ZETA * __log2f(u0));
                f1v.y = pref * exp2f(ZETA * __log2f(u1));
                f1v.z = pref * exp2f(ZETA * __log2f(u2));
                f1v.w = pref * exp2f(ZETA * __log2f(u3));
            }
            *(float4*)&s_f1[tid * 4] = f1v;               // 1 conflict-free STS.128
            s_sd[tid] = 0.5f * (dd0 * inv0 + dd1 * inv1); // 1 STS.32

            int s0 = (sg0 > 0) ? (sp0 & 7) : (sp0 >> 3);
            int s1 = (sg1 > 0) ? (sp1 & 7) : (sp1 >> 3);
            int a  = min(s0, s1);
            int bb = max(s0, s1);
            int tri = a * S - ((a * (a - 1)) >> 1) + (bb - a);
            s_base[tid] = c * COLS + ANG_OFF + tri * SUB;
        }
        __syncwarp();   // phase-2 reads only this warp's slice

        // warp phase: 4 triples per warp-instruction, 16B red.v4 per lane
        int lane = tid & 31;
        int warp = tid >> 5;
        int sub  = lane >> 3;     // triple slot 0..3
        int az   = lane & 7;      // shfa index 0..7
        float shfa = RAMIN + (float)az * DSTEP_A;
        int begin = warp * 32;
        int limit = T - t0;       // triples valid in this block (<=256)

        if (limit >= 256) {
            #pragma unroll
            for (int jj = 0; jj < 8; jj++) {
                int idx = begin + jj * 4 + sub;
                int base   = s_base[idx];                 // broadcast LDS
                float sd   = s_sd[idx];                   // broadcast LDS
                float4 f1v = *(const float4*)&s_f1[idx * 4];
                float dx  = sd - shfa;
                float f2v = exp2f(-ETA_A_LOG2E * dx * dx);
                float4 v = make_float4(f2v * f1v.x, f2v * f1v.y,
                                       f2v * f1v.z, f2v * f1v.w);
                RED4(out + base + az * 4, v);   // 8 lanes -> 128B contiguous
            }
        } else {
            #pragma unroll
            for (int jj = 0; jj < 8; jj++) {
                int idx = begin + jj * 4 + sub;
                if (idx < limit) {
                    int base   = s_base[idx];
                    float sd   = s_sd[idx];
                    float4 f1v = *(const float4*)&s_f1[idx * 4];
                    float dx  = sd - shfa;
                    float f2v = exp2f(-ETA_A_LOG2E * dx * dx);
                    float4 v = make_float4(f2v * f1v.x, f2v * f1v.y,
                                           f2v * f1v.z, f2v * f1v.w);
                    RED4(out + base + az * 4, v);
                }
            }
        }
    } else {
        // ---------------- radial partition: 4 lanes/pair, red.v4 ----------------
        int rid  = b - a_hi;                 // contiguous radial block id
        int rtid = rid * 256 + threadIdx.x;
        int p = rtid >> 2;
        if (p >= P) return;
        int m = rtid & 3;                    // bin group 0..3 (4 bins each)

        uint2 bse = g_base[p];               // coalesced 8B (uniform per group)
        float d   = __ldg(d_ij + p);

        // 0.25 * (0.5*cos + 0.5) = 0.125*cos + 0.125
        float fc = (d < RC) ? (0.125f * __cosf(PI_OVER_RC * d) + 0.125f) : 0.0f;
        int k0 = m * 4;
        float4 v;
        {
            float dx0 = d - (RMIN + (float)(k0 + 0) * DSTEP_R);
            float dx1 = d - (RMIN + (float)(k0 + 1) * DSTEP_R);
            float dx2 = d - (RMIN + (float)(k0 + 2) * DSTEP_R);
            float dx3 = d - (RMIN + (float)(k0 + 3) * DSTEP_R);
            v.x = fc * __expf(-ETA_R * dx0 * dx0);
            v.y = fc * __expf(-ETA_R * dx1 * dx1);
            v.z = fc * __expf(-ETA_R * dx2 * dx2);
            v.w = fc * __expf(-ETA_R * dx3 * dx3);
        }
        RED4(out + bse.x + k0, v);   // 4 lanes -> 64B contiguous
        RED4(out + bse.y + k0, v);
    }
}

// ---------------- launch ----------------
extern "C" void kernel_launch(void* const* d_in, const int* in_sizes, int n_in,
                              void* d_out, int out_size)
{
    const int*   atom_index = (const int*)  d_in[0];
    const int*   pairs      = (const int*)  d_in[1];
    const float* d_ij       = (const float*)d_in[2];
    const float* r_ij       = (const float*)d_in[3];
    const int*   central    = (const int*)  d_in[4];
    const int*   pidx12     = (const int*)  d_in[5];
    const int*   sign12     = (const int*)  d_in[6];
    float* out = (float*)d_out;

    int P  = in_sizes[2];                 // pair count
    int T  = in_sizes[4];                 // triple count
    int PA = PA_CONST;
    if (PA > P) PA = P;

    // kernel A: zero-fill || prep (all P pairs)
    int n4 = out_size / 4;
    int zblocks = 4736;
    int pblocks = (P + 255) / 256;
    fusedA_kernel<<<zblocks + pblocks, 256>>>(atom_index, pairs, d_ij, r_ij,
                                              (float4*)d_out, P, PA, zblocks, n4);

    // kernel B: angular || radial, Bresenham-interleaved
    int ablocks = (T + 255) / 256;
    int rblocks = (P * 4 + 255) / 256;    // 4 lanes per pair
    int total   = ablocks + rblocks;
    fusedB_kernel<<<total, 256>>>(central, pidx12, sign12, d_ij,
                                  out, P, T, ablocks, total);
}

// round 13
// speedup vs baseline: 1.0258x; 1.0258x over previous
#include <cuda_runtime.h>
#include <cstdint>

// ---------------- problem constants ----------------
#define NATOMS   50000
#define S        7
#define NRBF     16
#define NPAIRS   28        // S*(S+1)/2
#define SUB      32        // NA*NZ
#define COLS     1008      // S*NRBF + NPAIRS*SUB
#define COLS4    252
#define ANG_OFF  112       // S*NRBF
#define RC       0.51f
#define RMIN     0.08f
#define RCA      0.35f
#define RAMIN    0.08f
#define NA       8
#define NZ       4
#define ETA_R    1970.0f
#define ZETA     14.1f
#define PI_F     3.14159265358979323846f
#define PI_OVER_RC   (PI_F / RC)
#define PI_OVER_RCA  (PI_F / RCA)
#define DSTEP_R  0.026875f       // (RC-RMIN)/NRBF
#define DSTEP_A  0.03375f        // (RCA-RAMIN)/NA
#define ETA_A_LOG2E 1803.3688011112043f  // ETA_A * log2(e)

#define MAXP     1000000
#define PA_CONST 200000
#define CPB      8               // centers per angular owner-block

// vector float atomic (sm_90+): one 16B reduction per lane
#define RED4(ptr, v)                                                          \
    asm volatile("red.global.add.v4.f32 [%0], {%1,%2,%3,%4};"                 \
                 :: "l"(ptr), "f"((v).x), "f"((v).y), "f"((v).z), "f"((v).w)  \
                 : "memory")

// 16B record per angular pair: (rx, ry, rz, fc-with-spec-in-low-6-mantissa-bits)
__device__ float4 g_rec[PA_CONST];
// radial scatter bases per pair
__device__ uint2  g_base[MAXP];
// triple-segment start offset per center (lower_bound of sorted central[])
__device__ int    g_start[NATOMS + 1];

// ======= kernel A: radial zero || center offsets || per-pair precompute =======
__global__ __launch_bounds__(256)
void fusedA_kernel(const int* __restrict__ atom_index,
                   const int* __restrict__ pairs,   // [2, P]
                   const float* __restrict__ d_ij,  // [P]
                   const float* __restrict__ r_ij,  // [P,3]
                   const int* __restrict__ central, // [T] sorted
                   float4* __restrict__ out4,
                   int P, int PA, int T, int zblocks, int sblocks)
{
    int b = blockIdx.x;
    if (b < zblocks) {
        // zero radial strips only: NATOMS*28 float4 (cols [0,112) of each row)
        int idx = b * 256 + threadIdx.x;
        if (idx < NATOMS * 28) {
            int atom = idx / 28;
            int c4   = idx - atom * 28;
            out4[atom * COLS4 + c4] = make_float4(0.f, 0.f, 0.f, 0.f);
        }
        return;
    }
    if (b < zblocks + sblocks) {
        // lower_bound(central, a) for a in [0, NATOMS]
        int a = (b - zblocks) * 256 + threadIdx.x;
        if (a <= NATOMS) {
            int lo = 0, hi = T;
            while (lo < hi) {
                int mid = (lo + hi) >> 1;
                if (central[mid] < a) lo = mid + 1; else hi = mid;
            }
            g_start[a] = lo;
        }
        return;
    }
    int p = (b - zblocks - sblocks) * 256 + threadIdx.x;
    if (p >= P) return;

    int i  = pairs[p];
    int j  = pairs[P + p];
    int si = atom_index[i];
    int sj = atom_index[j];

    g_base[p] = make_uint2((unsigned)(i * COLS + sj * NRBF),
                           (unsigned)(j * COLS + si * NRBF));

    if (p < PA) {
        float d  = d_ij[p];
        float fc = (d < RCA) ? (0.5f * __cosf(PI_OVER_RCA * d) + 0.5f) : 0.0f;
        unsigned u = (__float_as_uint(fc) & 0xFFFFFFC0u)
                   | (unsigned)((si << 3) | sj);
        g_rec[p] = make_float4(r_ij[3 * p + 0], r_ij[3 * p + 1], r_ij[3 * p + 2],
                               __uint_as_float(u));
    }
}

// ======= kernel B: angular owner-blocks (zero + RED4) || radial (RED4) =======
__global__ __launch_bounds__(256)
void fusedB_kernel(const int* __restrict__ central,
                   const int* __restrict__ pidx,    // [2, T]
                   const int* __restrict__ sign12,  // [2, T]
                   const float* __restrict__ d_ij,
                   float* __restrict__ out,
                   int P, int T, int ablocks, int total)
{
    int b = blockIdx.x;
    // Bresenham split: angular blocks spread evenly through the grid
    int a_lo = (int)((long long)b * ablocks / total);
    int a_hi = (int)(((long long)b + 1) * ablocks / total);
    bool is_ang = (a_hi > a_lo);

    if (is_ang) {
        // ------------- angular owner-block: centers [c0, c0+8) -------------
        __shared__ __align__(16) float s_f1[256 * 4];   // pref*f1[zz], STS.128
        __shared__ float s_sd[256];                     // 0.5*(d0+d1)
        __shared__ int   s_base[256];

        int tid = threadIdx.x;
        int q   = a_lo;
        int c0  = q * CPB;

        // zero my 8 angular strips: 8*896 floats = 1792 float4, 7 per thread
        {
            float4* out4 = (float4*)out;
            #pragma unroll
            for (int k = 0; k < 7; k++) {
                int idx = tid + k * 256;       // 0..1791
                int lc  = idx / 224;           // 224 float4 per center strip
                int w4  = idx - lc * 224;
                out4[(c0 + lc) * COLS4 + 28 + w4] =
                    make_float4(0.f, 0.f, 0.f, 0.f);
            }
        }
        int seg_lo = g_start[c0];
        int seg_hi = g_start[c0 + CPB];
        __syncthreads();   // zeros visible before any RED from this block

        int lane = tid & 31;
        int warp = tid >> 5;
        int sub  = lane >> 3;     // triple slot 0..3
        int az   = lane & 7;      // shfa index 0..7
        float shfa = RAMIN + (float)az * DSTEP_A;

        for (int wlo = seg_lo; wlo < seg_hi; wlo += 256) {
            int t = wlo + tid;
            if (t < seg_hi) {
                // -------- phase 1: per-triple scalar --------
                int p0  = pidx[t];
                int p1  = pidx[T + t];
                int sg0 = sign12[t];
                int sg1 = sign12[T + t];
                int c   = central[t];

                float4 r0 = g_rec[p0];      // one scattered LDG.128 each
                float4 r1 = g_rec[p1];

                float dd0 = fmaf(r0.x, r0.x, fmaf(r0.y, r0.y, r0.z * r0.z));
                float dd1 = fmaf(r1.x, r1.x, fmaf(r1.y, r1.y, r1.z * r1.z));
                float inv0 = rsqrtf(dd0);
                float inv1 = rsqrtf(dd1);

                unsigned b0 = __float_as_uint(r0.w);
                unsigned b1 = __float_as_uint(r1.w);
                int   sp0 = (int)(b0 & 63u);
                int   sp1 = (int)(b1 & 63u);
                float fc0 = __uint_as_float(b0 & 0xFFFFFFC0u);
                float fc1 = __uint_as_float(b1 & 0xFFFFFFC0u);

                float dot  = r0.x * r1.x + r0.y * r1.y + r0.z * r1.z;
                float ss   = (sg0 == sg1) ? 0.95f : -0.95f;
                float cosa = ss * dot * inv0 * inv1;
                float sina = sqrtf(fmaxf(0.0f, 1.0f - cosa * cosa));
                float pref = 2.0f * fc0 * fc1;

                const float CZ[4] = { 0.92387953251f,  0.38268343236f,
                                     -0.38268343236f, -0.92387953251f };
                const float SZ[4] = { 0.38268343236f,  0.92387953251f,
                                      0.92387953251f,  0.38268343236f };
                float4 f1v;
                {
                    float u0 = fmaxf(0.0f, fmaf(0.5f * CZ[0], cosa, fmaf(0.5f * SZ[0], sina, 0.5f)));
                    float u1 = fmaxf(0.0f, fmaf(0.5f * CZ[1], cosa, fmaf(0.5f * SZ[1], sina, 0.5f)));
                    float u2 = fmaxf(0.0f, fmaf(0.5f * CZ[2], cosa, fmaf(0.5f * SZ[2], sina, 0.5f)));
                    float u3 = fmaxf(0.0f, fmaf(0.5f * CZ[3], cosa, fmaf(0.5f * SZ[3], sina, 0.5f)));
                    f1v.x = pref * exp2f(ZETA * __log2f(u0));
                    f1v.y = pref * exp2f(ZETA * __log2f(u1));
                    f1v.z = pref * exp2f(ZETA * __log2f(u2));
                    f1v.w = pref * exp2f(ZETA * __log2f(u3));
                }
                *(float4*)&s_f1[tid * 4] = f1v;               // conflict-free STS.128
                s_sd[tid] = 0.5f * (dd0 * inv0 + dd1 * inv1); // STS.32

                int s0 = (sg0 > 0) ? (sp0 & 7) : (sp0 >> 3);
                int s1 = (sg1 > 0) ? (sp1 & 7) : (sp1 >> 3);
                int a  = min(s0, s1);
                int bb = max(s0, s1);
                int tri = a * S - ((a * (a - 1)) >> 1) + (bb - a);
                s_base[tid] = c * COLS + ANG_OFF + tri * SUB;
            }
            __syncwarp();   // phase-2 reads only this warp's slice

            // -------- phase 2: 4 triples per warp-instr, RED4 --------
            int begin = warp * 32;
            int limit = seg_hi - wlo;
            if (limit > 256) limit = 256;

            if (limit - begin >= 32) {
                #pragma unroll
                for (int jj = 0; jj < 8; jj++) {
                    int idx = begin + jj * 4 + sub;
                    int base   = s_base[idx];
                    float sd   = s_sd[idx];
                    float4 f1v = *(const float4*)&s_f1[idx * 4];
                    float dx  = sd - shfa;
                    float f2v = exp2f(-ETA_A_LOG2E * dx * dx);
                    float4 v = make_float4(f2v * f1v.x, f2v * f1v.y,
                                           f2v * f1v.z, f2v * f1v.w);
                    RED4(out + base + az * 4, v);   // 8 lanes -> 128B line
                }
            } else {
                #pragma unroll
                for (int jj = 0; jj < 8; jj++) {
                    int idx = begin + jj * 4 + sub;
                    if (idx < limit) {
                        int base   = s_base[idx];
                        float sd   = s_sd[idx];
                        float4 f1v = *(const float4*)&s_f1[idx * 4];
                        float dx  = sd - shfa;
                        float f2v = exp2f(-ETA_A_LOG2E * dx * dx);
                        float4 v = make_float4(f2v * f1v.x, f2v * f1v.y,
                                               f2v * f1v.z, f2v * f1v.w);
                        RED4(out + base + az * 4, v);
                    }
                }
            }
            __syncwarp();   // before next chunk overwrites this warp's slice
        }
    } else {
        // ---------------- radial partition: 4 lanes/pair, red.v4 ----------------
        int rid  = b - a_hi;                 // contiguous radial block id
        int rtid = rid * 256 + threadIdx.x;
        int p = rtid >> 2;
        if (p >= P) return;
        int m = rtid & 3;                    // bin group 0..3 (4 bins each)

        uint2 bse = g_base[p];               // coalesced 8B (uniform per group)
        float d   = __ldg(d_ij + p);

        // 0.25 * (0.5*cos + 0.5) = 0.125*cos + 0.125
        float fc = (d < RC) ? (0.125f * __cosf(PI_OVER_RC * d) + 0.125f) : 0.0f;
        int k0 = m * 4;
        float4 v;
        {
            float dx0 = d - (RMIN + (float)(k0 + 0) * DSTEP_R);
            float dx1 = d - (RMIN + (float)(k0 + 1) * DSTEP_R);
            float dx2 = d - (RMIN + (float)(k0 + 2) * DSTEP_R);
            float dx3 = d - (RMIN + (float)(k0 + 3) * DSTEP_R);
            v.x = fc * __expf(-ETA_R * dx0 * dx0);
            v.y = fc * __expf(-ETA_R * dx1 * dx1);
            v.z = fc * __expf(-ETA_R * dx2 * dx2);
            v.w = fc * __expf(-ETA_R * dx3 * dx3);
        }
        RED4(out + bse.x + k0, v);   // 4 lanes -> 64B contiguous
        RED4(out + bse.y + k0, v);
    }
}

// ---------------- launch ----------------
extern "C" void kernel_launch(void* const* d_in, const int* in_sizes, int n_in,
                              void* d_out, int out_size)
{
    const int*   atom_index = (const int*)  d_in[0];
    const int*   pairs      = (const int*)  d_in[1];
    const float* d_ij       = (const float*)d_in[2];
    const float* r_ij       = (const float*)d_in[3];
    const int*   central    = (const int*)  d_in[4];
    const int*   pidx12     = (const int*)  d_in[5];
    const int*   sign12     = (const int*)  d_in[6];
    float* out = (float*)d_out;

    int P  = in_sizes[2];                 // pair count
    int T  = in_sizes[4];                 // triple count
    int PA = PA_CONST;
    if (PA > P) PA = P;

    // kernel A: radial zero || center start offsets || prep
    int zblocks = (NATOMS * 28 + 255) / 256;       // 5469
    int sblocks = (NATOMS + 1 + 255) / 256;        // 196
    int pblocks = (P + 255) / 256;
    fusedA_kernel<<<zblocks + sblocks + pblocks, 256>>>(
        atom_index, pairs, d_ij, r_ij, central,
        (float4*)d_out, P, PA, T, zblocks, sblocks);

    // kernel B: angular owner-blocks || radial, Bresenham-interleaved
    int ablocks = NATOMS / CPB;                    // 6250
    int rblocks = (P * 4 + 255) / 256;             // 4 lanes per pair
    int total   = ablocks + rblocks;
    fusedB_kernel<<<total, 256>>>(central, pidx12, sign12, d_ij,
                                  out, P, T, ablocks, total);
}